// round 1
// baseline (speedup 1.0000x reference)
#include <cuda_runtime.h>

#define BB 2
#define NN 20000
#define SS 1024
#define CC 256
#define NSS 16
#define OUTC 96

// smem layout constants (floats)
#define STRIDE 20                 // activation row stride (conflict-mitigating, float4-aligned)
#define BUFA_ROWS 272             // 259 rounded to 17 tiles * 16
#define BUFA_F (BUFA_ROWS*STRIDE) // 5440
#define BUFB_F (512*STRIDE)       // 10240
#define WT_F   (512*17)           // 8704
#define SMEM_FLOATS (BUFA_F + BUFB_F + WT_F + 256 + 256 + 32)
#define SMEM_BYTES  (SMEM_FLOATS*4)

// ---------------------------------------------------------------------------
// 16-row GEMM: outT[o][n] = relu(bn( sum_k inT[k][n]*W[o][k] + bias[o] ))
// inT: smem [Krows][STRIDE] (n in 0..15), W: global [OC][K] row-major.
// Thread map: rg = tid>>6 (4 row-groups of 4 rows), cg = tid&63,
// each thread owns NJ output channels o = cg + 64*j  (OC = 64*NJ).
// Weight tile staged as Wt[o][17] -> compute LDS stride 17 = conflict-free.
// ---------------------------------------------------------------------------
template<int NJ>
__device__ __forceinline__ void gemm16(
    const float* __restrict__ inT, const float* __restrict__ W,
    const float* __restrict__ bias, const float* __restrict__ gain,
    const float* __restrict__ beta, float* __restrict__ outT,
    float* __restrict__ Wt, int K, int tid)
{
    const int OC = NJ * 64;
    const int rg = tid >> 6;
    const int cg = tid & 63;
    float acc[4][NJ];
#pragma unroll
    for (int i = 0; i < 4; ++i)
#pragma unroll
        for (int j = 0; j < NJ; ++j) acc[i][j] = 0.f;

    const int ntiles = (K + 15) >> 4;
    for (int t = 0; t < ntiles; ++t) {
        const int k0 = t << 4;
        __syncthreads();
        // stage Wt[OC][16] (pad 17), zero-fill past K
        for (int i = tid; i < OC * 16; i += 256) {
            int o = i >> 4, k = i & 15;
            int kk = k0 + k;
            Wt[o * 17 + k] = (kk < K) ? W[o * K + kk] : 0.f;
        }
        __syncthreads();
#pragma unroll
        for (int kk = 0; kk < 16; ++kk) {
            float4 h4 = *reinterpret_cast<const float4*>(inT + (k0 + kk) * STRIDE + rg * 4);
#pragma unroll
            for (int j = 0; j < NJ; ++j) {
                float w = Wt[(cg + 64 * j) * 17 + kk];
                acc[0][j] = fmaf(h4.x, w, acc[0][j]);
                acc[1][j] = fmaf(h4.y, w, acc[1][j]);
                acc[2][j] = fmaf(h4.z, w, acc[2][j]);
                acc[3][j] = fmaf(h4.w, w, acc[3][j]);
            }
        }
    }
    const float inv = rsqrtf(1.f + 1e-5f);
#pragma unroll
    for (int j = 0; j < NJ; ++j) {
        int o = cg + 64 * j;
        float sc = gain[o] * inv;
        float bb = bias[o];
        float bt = beta[o];
#pragma unroll
        for (int i = 0; i < 4; ++i) {
            float v = (acc[i][j] + bb) * sc + bt;
            outT[o * STRIDE + rg * 4 + i] = fmaxf(v, 0.f);
        }
    }
}

// ---------------------------------------------------------------------------
// vector-matrix head layer: out[o] = (opt relu(bn(...))) sum_c v[c]*W[o][c]+b[o]
// one output channel per thread; staged tiles for coalesced W reads.
// ---------------------------------------------------------------------------
__device__ __forceinline__ void vecmat(
    const float* __restrict__ v, const float* __restrict__ W,
    const float* __restrict__ bias, const float* __restrict__ gain,
    const float* __restrict__ beta, float* __restrict__ out,
    float* __restrict__ Wt, int K, int OC, bool do_bnrelu, int tid)
{
    float acc = 0.f;
    const int ntiles = K >> 4;
    for (int t = 0; t < ntiles; ++t) {
        const int k0 = t << 4;
        __syncthreads();
        for (int i = tid; i < OC * 16; i += 256) {
            int o = i >> 4, k = i & 15;
            Wt[o * 17 + k] = W[o * K + k0 + k];
        }
        __syncthreads();
        if (tid < OC) {
#pragma unroll
            for (int kk = 0; kk < 16; ++kk)
                acc = fmaf(v[k0 + kk], Wt[tid * 17 + kk], acc);
        }
    }
    if (tid < OC) {
        float val = acc + bias[tid];
        if (do_bnrelu) {
            val = val * (gain[tid] * rsqrtf(1.f + 1e-5f)) + beta[tid];
            val = fmaxf(val, 0.f);
        }
        out[tid] = val;
    }
}

__global__ void __launch_bounds__(256)
grasp_kernel(
    const float* __restrict__ xyz, const float* __restrict__ new_xyz,
    const float* __restrict__ view_rot, const float* __restrict__ features,
    const float* __restrict__ w1, const float* __restrict__ b1,
    const float* __restrict__ g1, const float* __restrict__ be1,
    const float* __restrict__ w2, const float* __restrict__ b2,
    const float* __restrict__ g2, const float* __restrict__ be2,
    const float* __restrict__ w3, const float* __restrict__ b3,
    const float* __restrict__ g3, const float* __restrict__ be3,
    const float* __restrict__ cw1, const float* __restrict__ cb1,
    const float* __restrict__ cg1, const float* __restrict__ cbe1,
    const float* __restrict__ cw2, const float* __restrict__ cb2,
    const float* __restrict__ cg2, const float* __restrict__ cbe2,
    const float* __restrict__ cw3, const float* __restrict__ cb3,
    float* __restrict__ out)
{
    extern __shared__ float sm[];
    float* bufA = sm;                   // [272][20] activations (h / L2-out)
    float* bufB = bufA + BUFA_F;        // [512][20] activations (L1-out / L3-out)
    float* Wt   = bufB + BUFB_F;        // [512][17] weight tile
    float* mvec = Wt + WT_F;            // [256]
    float* vvec = mvec + 256;           // [256]
    int* s_idx   = (int*)(vvec + 256);  // [16]
    int* warpcnt = s_idx + 16;          // [8]
    int* s_found = warpcnt + 8;         // [1]

    const int tid = threadIdx.x;
    const int s = blockIdx.x, b = blockIdx.y;
    const long q = (long)b * SS + s;

    // per-query rotation + center (broadcast loads)
    const float* vr = view_rot + q * 9;
    float R00 = vr[0], R01 = vr[1], R02 = vr[2];
    float R10 = vr[3], R11 = vr[4], R12 = vr[5];
    float R20 = vr[6], R21 = vr[7], R22 = vr[8];
    float qx = new_xyz[q * 3 + 0], qy = new_xyz[q * 3 + 1], qz = new_xyz[q * 3 + 2];
    float d0 = R00 * qx + R01 * qy + R02 * qz;
    float d1 = R10 * qx + R11 * qy + R12 * qz;
    float d2 = R20 * qx + R21 * qy + R22 * qz;

    // zero h buffer (covers k-padding rows 259..271 for layer1)
    for (int i = tid; i < BUFA_F; i += 256) bufA[i] = 0.f;
    if (tid == 0) s_found[0] = 0;
    __syncthreads();

    // ---- ball query: first NS masked indices in ascending order ----
    const float* xb = xyz + (long)b * NN * 3;
    for (int p0 = 0; p0 < NN; p0 += 256) {
        int fnd = s_found[0];
        if (fnd >= NSS) break;
        int p = p0 + tid;
        bool mk = false;
        if (p < NN) {
            float x = xb[p * 3 + 0], y = xb[p * 3 + 1], z = xb[p * 3 + 2];
            float xr = fmaf(R00, x, fmaf(R01, y, R02 * z)) - d0;
            float yr = fmaf(R10, x, fmaf(R11, y, R12 * z)) - d1;
            float zr = fmaf(R20, x, fmaf(R21, y, R22 * z)) - d2;
            mk = (yr * yr + zr * zr < 0.05f * 0.05f) && (xr > -0.02f) && (xr < 0.04f);
        }
        unsigned bal = __ballot_sync(0xffffffffu, mk);
        if ((tid & 31) == 0) warpcnt[tid >> 5] = __popc(bal);
        __syncthreads();
        int pre = 0, tot = 0;
#pragma unroll
        for (int w = 0; w < 8; ++w) {
            int c = warpcnt[w];
            tot += c;
            if (w < (tid >> 5)) pre += c;
        }
        if (mk) {
            int slot = fnd + pre + __popc(bal & ((1u << (tid & 31)) - 1u));
            if (slot < NSS) s_idx[slot] = p;
        }
        __syncthreads();
        if (tid == 0) s_found[0] = fnd + tot;
        __syncthreads();
    }
    {
        int f = min(s_found[0], NSS);
        if (tid < NSS && tid >= f) s_idx[tid] = (f == 0) ? 0 : s_idx[0];
    }
    __syncthreads();

    // ---- build h: rows 0..2 rotated local coords, rows 3..258 features ----
    if (tid < NSS) {
        int p = s_idx[tid];
        float gx = xb[p * 3 + 0], gy = xb[p * 3 + 1], gz = xb[p * 3 + 2];
        float dx = (gx - qx) / 0.05f;
        float dy = (gy - qy) / 0.05f;
        float dz = (gz - qz) / 0.05f;
        bufA[0 * STRIDE + tid] = dx * R00 + dy * R10 + dz * R20;
        bufA[1 * STRIDE + tid] = dx * R01 + dy * R11 + dz * R21;
        bufA[2 * STRIDE + tid] = dx * R02 + dy * R12 + dz * R22;
    }
    const float* fb = features + (long)b * CC * NN;
    for (int i = tid; i < CC * NSS; i += 256) {
        int c = i >> 4, n = i & 15;
        bufA[(3 + c) * STRIDE + n] = fb[(long)c * NN + s_idx[n]];
    }

    // ---- MLP stack (syncthreads at each tile boundary covers hazards) ----
    gemm16<8>(bufA, w1, b1, g1, be1, bufB, Wt, 259, tid);   // 259 -> 512
    gemm16<4>(bufB, w2, b2, g2, be2, bufA, Wt, 512, tid);   // 512 -> 256
    gemm16<4>(bufA, w3, b3, g3, be3, bufB, Wt, 256, tid);   // 256 -> 256
    __syncthreads();

    // ---- max over the 16 neighbors ----
    {
        float mx = bufB[tid * STRIDE + 0];
#pragma unroll
        for (int n = 1; n < NSS; ++n) mx = fmaxf(mx, bufB[tid * STRIDE + n]);
        mvec[tid] = mx;
    }

    // ---- head layers ----
    vecmat(mvec, cw1, cb1, cg1, cbe1, vvec, Wt, 256, 256, true, tid);
    vecmat(vvec, cw2, cb2, cg2, cbe2, mvec, Wt, 256, 256, true, tid);
    vecmat(mvec, cw3, cb3, nullptr, nullptr, out + q * OUTC, Wt, 256, OUTC, false, tid);
}

extern "C" void kernel_launch(void* const* d_in, const int* in_sizes, int n_in,
                              void* d_out, int out_size)
{
    const float* xyz      = (const float*)d_in[0];
    const float* new_xyz  = (const float*)d_in[1];
    const float* view_rot = (const float*)d_in[2];
    const float* features = (const float*)d_in[3];
    const float* w1  = (const float*)d_in[4];
    const float* b1  = (const float*)d_in[5];
    const float* g1  = (const float*)d_in[6];
    const float* be1 = (const float*)d_in[7];
    const float* w2  = (const float*)d_in[8];
    const float* b2  = (const float*)d_in[9];
    const float* g2  = (const float*)d_in[10];
    const float* be2 = (const float*)d_in[11];
    const float* w3  = (const float*)d_in[12];
    const float* b3  = (const float*)d_in[13];
    const float* g3  = (const float*)d_in[14];
    const float* be3 = (const float*)d_in[15];
    const float* cw1 = (const float*)d_in[16];
    const float* cb1 = (const float*)d_in[17];
    const float* cg1 = (const float*)d_in[18];
    const float* cbe1= (const float*)d_in[19];
    const float* cw2 = (const float*)d_in[20];
    const float* cb2 = (const float*)d_in[21];
    const float* cg2 = (const float*)d_in[22];
    const float* cbe2= (const float*)d_in[23];
    const float* cw3 = (const float*)d_in[24];
    const float* cb3 = (const float*)d_in[25];
    float* out = (float*)d_out;

    cudaFuncSetAttribute(grasp_kernel,
                         cudaFuncAttributeMaxDynamicSharedMemorySize, SMEM_BYTES);

    dim3 grid(SS, BB);
    grasp_kernel<<<grid, 256, SMEM_BYTES>>>(
        xyz, new_xyz, view_rot, features,
        w1, b1, g1, be1, w2, b2, g2, be2, w3, b3, g3, be3,
        cw1, cb1, cg1, cbe1, cw2, cb2, cg2, cbe2, cw3, cb3, out);
}

// round 2
// speedup vs baseline: 3.4459x; 3.4459x over previous
#include <cuda_runtime.h>
#include <cuda_fp16.h>

#define BB 2
#define NN 20000
#define SS 1024
#define CC 256
#define NSS 16
#define OUTC 96
#define MROWS (BB*SS*NSS)   /* 32768 */
#define K1P 288             /* 259 padded to multiple of 32 */

// ---------------- scratch (static device globals; no runtime alloc) --------
__device__ __half g_featT[(size_t)BB*NN*CC];     // [b][n][c] fp16
__device__ __half g_H0[(size_t)MROWS*K1P];       // layer-1 input
__device__ __half g_act1[(size_t)MROWS*512];
__device__ __half g_act2[(size_t)MROWS*256];
__device__ float  g_act3[(size_t)MROWS*256];
__device__ __half g_w1h[512*K1P];
__device__ __half g_w2h[256*512];
__device__ __half g_w3h[256*256];

// ---------------- weight prep: fp32 -> fp16 (+ column permutation for W1) --
__global__ void prep_weights(const float* __restrict__ w1,
                             const float* __restrict__ w2,
                             const float* __restrict__ w3)
{
    int i = blockIdx.x * 256 + threadIdx.x;
    if (i < 512 * K1P) {
        int o = i / K1P, k = i % K1P;
        float v = 0.f;
        if (k < 256)      v = w1[o * 259 + 3 + k];      // features
        else if (k < 259) v = w1[o * 259 + (k - 256)];  // coords
        g_w1h[i] = __float2half(v);
    }
    int j = i - 512 * K1P;
    if (j >= 0 && j < 256 * 512) g_w2h[j] = __float2half(w2[j]);
    int l = i - 512 * K1P - 256 * 512;
    if (l >= 0 && l < 256 * 256) g_w3h[l] = __float2half(w3[l]);
}

// ---------------- transpose features [b][c][n] -> featT [b][n][c] fp16 -----
__global__ void transpose_feat(const float* __restrict__ feat)
{
    __shared__ float tile[32][33];
    int b = blockIdx.z, n0 = blockIdx.x * 32, c0 = blockIdx.y * 32;
    int tx = threadIdx.x, ty = threadIdx.y;
    const float* fb = feat + (size_t)b * CC * NN;
#pragma unroll
    for (int i = 0; i < 4; ++i) {
        int c = c0 + ty + i * 8;
        tile[ty + i * 8][tx] = fb[(size_t)c * NN + n0 + tx];
    }
    __syncthreads();
    __half* ft = g_featT + (size_t)b * NN * CC;
#pragma unroll
    for (int i = 0; i < 4; ++i) {
        int n = n0 + ty + i * 8;
        ft[(size_t)n * CC + c0 + tx] = __float2half(tile[tx][ty + i * 8]);
    }
}

// ---------------- ball query + gather into H0 ------------------------------
__global__ void __launch_bounds__(256)
gather_kernel(const float* __restrict__ xyz, const float* __restrict__ new_xyz,
              const float* __restrict__ view_rot)
{
    __shared__ int   s_cand[8 * 16];
    __shared__ int   s_cnt[8];
    __shared__ int   s_idx[16];
    __shared__ float s_co[16 * 3];

    const int q = blockIdx.x;
    const int b = q >> 10;
    const int tid = threadIdx.x, lane = tid & 31, w = tid >> 5;

    const float* vr = view_rot + (size_t)q * 9;
    float R00 = vr[0], R01 = vr[1], R02 = vr[2];
    float R10 = vr[3], R11 = vr[4], R12 = vr[5];
    float R20 = vr[6], R21 = vr[7], R22 = vr[8];
    float qx = new_xyz[q * 3 + 0], qy = new_xyz[q * 3 + 1], qz = new_xyz[q * 3 + 2];
    float d0 = R00 * qx + R01 * qy + R02 * qz;
    float d1 = R10 * qx + R11 * qy + R12 * qz;
    float d2 = R20 * qx + R21 * qy + R22 * qz;

    const float* xb = xyz + (size_t)b * NN * 3;

    // warp-parallel ordered compaction: warp w scans [w*2500, (w+1)*2500)
    const int start = w * 2500;
    int cnt = 0;
    for (int i = 0; i < 79 && cnt < 16; ++i) {
        int p = start + i * 32 + lane;
        bool mk = false;
        if (p < start + 2500) {
            float x = xb[p * 3 + 0], y = xb[p * 3 + 1], z = xb[p * 3 + 2];
            float xr = fmaf(R00, x, fmaf(R01, y, R02 * z)) - d0;
            float yr = fmaf(R10, x, fmaf(R11, y, R12 * z)) - d1;
            float zr = fmaf(R20, x, fmaf(R21, y, R22 * z)) - d2;
            mk = (yr * yr + zr * zr < 0.05f * 0.05f) && (xr > -0.02f) && (xr < 0.04f);
        }
        unsigned bal = __ballot_sync(0xffffffffu, mk);
        if (bal) {
            int pos = cnt + __popc(bal & ((1u << lane) - 1u));
            if (mk && pos < 16) s_cand[w * 16 + pos] = p;
            cnt += __popc(bal);
        }
    }
    if (lane == 0) s_cnt[w] = cnt < 16 ? cnt : 16;
    __syncthreads();

    if (tid == 0) {
        int tot = 0;
        for (int ww = 0; ww < 8 && tot < 16; ++ww)
            for (int j = 0; j < s_cnt[ww] && tot < 16; ++j)
                s_idx[tot++] = s_cand[ww * 16 + j];
        if (tot == 0) { for (int j = 0; j < 16; ++j) s_idx[j] = 0; }
        else          { for (int j = tot; j < 16; ++j) s_idx[j] = s_idx[0]; }
    }
    __syncthreads();

    if (tid < 16) {
        int p = s_idx[tid];
        float gx = xb[p * 3 + 0], gy = xb[p * 3 + 1], gz = xb[p * 3 + 2];
        float dx = (gx - qx) / 0.05f;
        float dy = (gy - qy) / 0.05f;
        float dz = (gz - qz) / 0.05f;
        s_co[tid * 3 + 0] = dx * R00 + dy * R10 + dz * R20;
        s_co[tid * 3 + 1] = dx * R01 + dy * R11 + dz * R21;
        s_co[tid * 3 + 2] = dx * R02 + dy * R12 + dz * R22;
    }
    __syncthreads();

    __half* H = g_H0 + (size_t)q * 16 * K1P;
    // tail cols 256..287: coords (256..258) + zero pad
    for (int t = tid; t < 16 * 32; t += 256) {
        int n = t >> 5, c = 256 + (t & 31);
        float v = (c < 259) ? s_co[n * 3 + (c - 256)] : 0.f;
        H[n * K1P + c] = __float2half(v);
    }
    // feature cols 0..255 (coalesced 8B copies from featT)
    const __half* ft = g_featT + (size_t)b * NN * CC;
    for (int t = tid; t < 16 * 64; t += 256) {
        int n = t >> 6, cs = t & 63;
        uint2 v = *(const uint2*)(ft + (size_t)s_idx[n] * CC + cs * 4);
        *(uint2*)(H + n * K1P + cs * 4) = v;
    }
}

// ---------------- tensor-core GEMM:  C = relu(bn(A @ W^T + b)) --------------
__device__ __forceinline__ void ldsm_x4(unsigned& r0, unsigned& r1,
                                        unsigned& r2, unsigned& r3,
                                        const __half* p)
{
    unsigned a = (unsigned)__cvta_generic_to_shared(p);
    asm volatile("ldmatrix.sync.aligned.m8n8.x4.shared.b16 {%0,%1,%2,%3}, [%4];"
                 : "=r"(r0), "=r"(r1), "=r"(r2), "=r"(r3) : "r"(a));
}

__device__ __forceinline__ void mma16816(float* c, const unsigned* a,
                                         unsigned b0, unsigned b1)
{
    asm volatile(
        "mma.sync.aligned.m16n8k16.row.col.f32.f16.f16.f32 "
        "{%0,%1,%2,%3},{%4,%5,%6,%7},{%8,%9},{%0,%1,%2,%3};"
        : "+f"(c[0]), "+f"(c[1]), "+f"(c[2]), "+f"(c[3])
        : "r"(a[0]), "r"(a[1]), "r"(a[2]), "r"(a[3]), "r"(b0), "r"(b1));
}

// CTA tile 64(M) x 128(N), 8 warps (2x4), warp tile 32x32, K-step 32.
template<bool OUT_HALF>
__global__ void __launch_bounds__(256)
gemm_kernel(const __half* __restrict__ A, int lda,
            const __half* __restrict__ W, int ldw, int K,
            const float* __restrict__ bias, const float* __restrict__ gain,
            const float* __restrict__ beta, void* __restrict__ outp, int ldo)
{
    __shared__ __half As[64 * 40];
    __shared__ __half Ws[128 * 40];

    const int tid = threadIdx.x, lane = tid & 31, warp = tid >> 5;
    const int wm = warp & 1, wn = warp >> 1;
    const size_t m0 = (size_t)blockIdx.x * 64;
    const int n0 = blockIdx.y * 128;

    float acc[2][4][4] = {};

    const int r = tid >> 2, seg8 = (tid & 3) * 8;
    const __half* Ag  = A + (m0 + r) * lda + seg8;
    const __half* Wg0 = W + (size_t)(n0 + r) * ldw + seg8;
    const __half* Wg1 = Wg0 + (size_t)64 * ldw;

    uint4 aR  = *(const uint4*)Ag;
    uint4 w0R = *(const uint4*)Wg0;
    uint4 w1R = *(const uint4*)Wg1;

    const int KT = K >> 5;
    for (int kt = 0; kt < KT; ++kt) {
        *(uint4*)(As + r * 40 + seg8)        = aR;
        *(uint4*)(Ws + r * 40 + seg8)        = w0R;
        *(uint4*)(Ws + (r + 64) * 40 + seg8) = w1R;
        __syncthreads();
        if (kt + 1 < KT) {           // prefetch next tile into registers
            aR  = *(const uint4*)(Ag  + (kt + 1) * 32);
            w0R = *(const uint4*)(Wg0 + (kt + 1) * 32);
            w1R = *(const uint4*)(Wg1 + (kt + 1) * 32);
        }
#pragma unroll
        for (int kb = 0; kb < 32; kb += 16) {
            unsigned am[2][4];
#pragma unroll
            for (int mi = 0; mi < 2; ++mi)
                ldsm_x4(am[mi][0], am[mi][1], am[mi][2], am[mi][3],
                        As + (wm * 32 + mi * 16 + (lane & 15)) * 40 + kb + (lane >> 4) * 8);
            unsigned b0[4], b1[4];
#pragma unroll
            for (int p = 0; p < 2; ++p) {
                unsigned t0, t1, t2, t3;
                ldsm_x4(t0, t1, t2, t3,
                        Ws + (wn * 32 + p * 16 + (lane & 15)) * 40 + kb + (lane >> 4) * 8);
                b0[2 * p] = t0; b0[2 * p + 1] = t1;
                b1[2 * p] = t2; b1[2 * p + 1] = t3;
            }
#pragma unroll
            for (int mi = 0; mi < 2; ++mi)
#pragma unroll
                for (int ni = 0; ni < 4; ++ni)
                    mma16816(acc[mi][ni], am[mi], b0[ni], b1[ni]);
        }
        __syncthreads();
    }

    const float inv = rsqrtf(1.f + 1e-5f);
#pragma unroll
    for (int mi = 0; mi < 2; ++mi) {
        size_t row = m0 + wm * 32 + mi * 16 + (lane >> 2);
#pragma unroll
        for (int ni = 0; ni < 4; ++ni) {
            int col = n0 + wn * 32 + ni * 8 + (lane & 3) * 2;
            float s0 = gain[col] * inv,  s1 = gain[col + 1] * inv;
            float bi0 = bias[col],       bi1 = bias[col + 1];
            float be0 = beta[col],       be1 = beta[col + 1];
            float v00 = fmaxf(fmaf(acc[mi][ni][0] + bi0, s0, be0), 0.f);
            float v01 = fmaxf(fmaf(acc[mi][ni][1] + bi1, s1, be1), 0.f);
            float v10 = fmaxf(fmaf(acc[mi][ni][2] + bi0, s0, be0), 0.f);
            float v11 = fmaxf(fmaf(acc[mi][ni][3] + bi1, s1, be1), 0.f);
            if (OUT_HALF) {
                __half* o = (__half*)outp;
                *(__half2*)(o + row * ldo + col)       = __floats2half2_rn(v00, v01);
                *(__half2*)(o + (row + 8) * ldo + col) = __floats2half2_rn(v10, v11);
            } else {
                float* o = (float*)outp;
                *(float2*)(o + row * ldo + col)        = make_float2(v00, v01);
                *(float2*)(o + (row + 8) * ldo + col)  = make_float2(v10, v11);
            }
        }
    }
}

// ---------------- head: maxpool over 16 + c1/c2/c3 --------------------------
__device__ __forceinline__ void vecmat(
    const float* __restrict__ v, const float* __restrict__ W,
    const float* __restrict__ bias, const float* __restrict__ gain,
    const float* __restrict__ beta, float* __restrict__ out,
    float* __restrict__ Wt, int K, int OC, bool do_bnrelu, int tid)
{
    float acc = 0.f;
    const int ntiles = K >> 4;
    for (int t = 0; t < ntiles; ++t) {
        const int k0 = t << 4;
        __syncthreads();
        for (int i = tid; i < OC * 16; i += 256) {
            int o = i >> 4, k = i & 15;
            Wt[o * 17 + k] = W[o * K + k0 + k];
        }
        __syncthreads();
        if (tid < OC) {
#pragma unroll
            for (int kk = 0; kk < 16; ++kk)
                acc = fmaf(v[k0 + kk], Wt[tid * 17 + kk], acc);
        }
    }
    if (tid < OC) {
        float val = acc + bias[tid];
        if (do_bnrelu) {
            val = val * (gain[tid] * rsqrtf(1.f + 1e-5f)) + beta[tid];
            val = fmaxf(val, 0.f);
        }
        out[tid] = val;
    }
}

__global__ void __launch_bounds__(256)
head_kernel(const float* __restrict__ cw1, const float* __restrict__ cb1,
            const float* __restrict__ cg1, const float* __restrict__ cbe1,
            const float* __restrict__ cw2, const float* __restrict__ cb2,
            const float* __restrict__ cg2, const float* __restrict__ cbe2,
            const float* __restrict__ cw3, const float* __restrict__ cb3,
            float* __restrict__ out)
{
    __shared__ float Wt[256 * 17];
    __shared__ float va[256], vb[256];
    const int q = blockIdx.x, tid = threadIdx.x;

    const float* a3 = g_act3 + (size_t)q * 16 * 256;
    float mx = a3[tid];
#pragma unroll
    for (int n = 1; n < NSS; ++n) mx = fmaxf(mx, a3[n * 256 + tid]);
    va[tid] = mx;

    vecmat(va, cw1, cb1, cg1, cbe1, vb, Wt, 256, 256, true, tid);
    vecmat(vb, cw2, cb2, cg2, cbe2, va, Wt, 256, 256, true, tid);
    vecmat(va, cw3, cb3, nullptr, nullptr, out + (size_t)q * OUTC, Wt, 256, OUTC, false, tid);
}

// ---------------- launch ----------------------------------------------------
extern "C" void kernel_launch(void* const* d_in, const int* in_sizes, int n_in,
                              void* d_out, int out_size)
{
    const float* xyz      = (const float*)d_in[0];
    const float* new_xyz  = (const float*)d_in[1];
    const float* view_rot = (const float*)d_in[2];
    const float* features = (const float*)d_in[3];
    const float* w1  = (const float*)d_in[4];
    const float* b1  = (const float*)d_in[5];
    const float* g1  = (const float*)d_in[6];
    const float* be1 = (const float*)d_in[7];
    const float* w2  = (const float*)d_in[8];
    const float* b2  = (const float*)d_in[9];
    const float* g2  = (const float*)d_in[10];
    const float* be2 = (const float*)d_in[11];
    const float* w3  = (const float*)d_in[12];
    const float* b3  = (const float*)d_in[13];
    const float* g3  = (const float*)d_in[14];
    const float* be3 = (const float*)d_in[15];
    const float* cw1 = (const float*)d_in[16];
    const float* cb1 = (const float*)d_in[17];
    const float* cg1 = (const float*)d_in[18];
    const float* cbe1= (const float*)d_in[19];
    const float* cw2 = (const float*)d_in[20];
    const float* cb2 = (const float*)d_in[21];
    const float* cg2 = (const float*)d_in[22];
    const float* cbe2= (const float*)d_in[23];
    const float* cw3 = (const float*)d_in[24];
    const float* cb3 = (const float*)d_in[25];
    float* out = (float*)d_out;

    __half *fT, *h0, *a1, *a2, *w1h, *w2h, *w3h;
    float* a3;
    cudaGetSymbolAddress((void**)&fT,  g_featT);
    cudaGetSymbolAddress((void**)&h0,  g_H0);
    cudaGetSymbolAddress((void**)&a1,  g_act1);
    cudaGetSymbolAddress((void**)&a2,  g_act2);
    cudaGetSymbolAddress((void**)&a3,  g_act3);
    cudaGetSymbolAddress((void**)&w1h, g_w1h);
    cudaGetSymbolAddress((void**)&w2h, g_w2h);
    cudaGetSymbolAddress((void**)&w3h, g_w3h);

    prep_weights<<<1344, 256>>>(w1, w2, w3);
    transpose_feat<<<dim3(NN / 32, CC / 32, BB), dim3(32, 8)>>>(features);
    gather_kernel<<<BB * SS, 256>>>(xyz, new_xyz, view_rot);

    gemm_kernel<true ><<<dim3(MROWS / 64, 4), 256>>>(h0, K1P, w1h, K1P, K1P, b1, g1, be1, a1, 512);
    gemm_kernel<true ><<<dim3(MROWS / 64, 2), 256>>>(a1, 512, w2h, 512, 512, b2, g2, be2, a2, 256);
    gemm_kernel<false><<<dim3(MROWS / 64, 2), 256>>>(a2, 256, w3h, 256, 256, b3, g3, be3, a3, 256);

    head_kernel<<<BB * SS, 256>>>(cw1, cb1, cg1, cbe1, cw2, cb2, cg2, cbe2, cw3, cb3, out);
}

// round 3
// speedup vs baseline: 4.7490x; 1.3782x over previous
#include <cuda_runtime.h>
#include <cuda_fp16.h>

#define BB 2
#define NN 20000
#define SS 1024
#define CC 256
#define NSS 16
#define OUTC 96
#define MROWS (BB*SS*NSS)   /* 32768 */
#define K1P 288             /* 259 padded to multiple of 32 */

// ---------------- scratch (static device globals; no runtime alloc) --------
__device__ __half g_featT[(size_t)BB*NN*CC];     // [b][n][c] fp16
__device__ __half g_H0[(size_t)MROWS*K1P];       // layer-1 input
__device__ __half g_act1[(size_t)MROWS*512];
__device__ __half g_act2[(size_t)MROWS*256];
__device__ float  g_act3[(size_t)MROWS*256];
__device__ __half g_w1h[512*K1P];
__device__ __half g_w2h[256*512];
__device__ __half g_w3h[256*256];

// ---------------- weight prep: fp32 -> fp16 (+ column permutation for W1) --
__global__ void prep_weights(const float* __restrict__ w1,
                             const float* __restrict__ w2,
                             const float* __restrict__ w3)
{
    int i = blockIdx.x * 256 + threadIdx.x;
    if (i < 512 * K1P) {
        int o = i / K1P, k = i % K1P;
        float v = 0.f;
        if (k < 256)      v = w1[o * 259 + 3 + k];      // features
        else if (k < 259) v = w1[o * 259 + (k - 256)];  // coords
        g_w1h[i] = __float2half(v);
    }
    int j = i - 512 * K1P;
    if (j >= 0 && j < 256 * 512) g_w2h[j] = __float2half(w2[j]);
    int l = i - 512 * K1P - 256 * 512;
    if (l >= 0 && l < 256 * 256) g_w3h[l] = __float2half(w3[l]);
}

// ---------------- transpose features [b][c][n] -> featT [b][n][c] fp16 -----
__global__ void transpose_feat(const float* __restrict__ feat)
{
    __shared__ float tile[32][33];
    int b = blockIdx.z, n0 = blockIdx.x * 32, c0 = blockIdx.y * 32;
    int tx = threadIdx.x, ty = threadIdx.y;
    const float* fb = feat + (size_t)b * CC * NN;
#pragma unroll
    for (int i = 0; i < 4; ++i) {
        int c = c0 + ty + i * 8;
        tile[ty + i * 8][tx] = fb[(size_t)c * NN + n0 + tx];
    }
    __syncthreads();
    __half* ft = g_featT + (size_t)b * NN * CC;
#pragma unroll
    for (int i = 0; i < 4; ++i) {
        int n = n0 + ty + i * 8;
        ft[(size_t)n * CC + c0 + tx] = __float2half(tile[tx][ty + i * 8]);
    }
}

// ---------------- ball query + gather into H0 ------------------------------
__global__ void __launch_bounds__(256)
gather_kernel(const float* __restrict__ xyz, const float* __restrict__ new_xyz,
              const float* __restrict__ view_rot)
{
    __shared__ int   s_cand[8 * 16];
    __shared__ int   s_cnt[8];
    __shared__ int   s_idx[16];
    __shared__ float s_co[16 * 3];

    const int q = blockIdx.x;
    const int b = q >> 10;
    const int tid = threadIdx.x, lane = tid & 31, w = tid >> 5;

    const float* vr = view_rot + (size_t)q * 9;
    float R00 = vr[0], R01 = vr[1], R02 = vr[2];
    float R10 = vr[3], R11 = vr[4], R12 = vr[5];
    float R20 = vr[6], R21 = vr[7], R22 = vr[8];
    float qx = new_xyz[q * 3 + 0], qy = new_xyz[q * 3 + 1], qz = new_xyz[q * 3 + 2];
    float d0 = R00 * qx + R01 * qy + R02 * qz;
    float d1 = R10 * qx + R11 * qy + R12 * qz;
    float d2 = R20 * qx + R21 * qy + R22 * qz;

    const float* xb = xyz + (size_t)b * NN * 3;

    // warp-parallel ordered compaction: warp w scans [w*2500, (w+1)*2500)
    const int start = w * 2500;
    int cnt = 0;
    for (int i = 0; i < 79 && cnt < 16; ++i) {
        int p = start + i * 32 + lane;
        bool mk = false;
        if (p < start + 2500) {
            float x = xb[p * 3 + 0], y = xb[p * 3 + 1], z = xb[p * 3 + 2];
            float xr = fmaf(R00, x, fmaf(R01, y, R02 * z)) - d0;
            float yr = fmaf(R10, x, fmaf(R11, y, R12 * z)) - d1;
            float zr = fmaf(R20, x, fmaf(R21, y, R22 * z)) - d2;
            mk = (yr * yr + zr * zr < 0.05f * 0.05f) && (xr > -0.02f) && (xr < 0.04f);
        }
        unsigned bal = __ballot_sync(0xffffffffu, mk);
        if (bal) {
            int pos = cnt + __popc(bal & ((1u << lane) - 1u));
            if (mk && pos < 16) s_cand[w * 16 + pos] = p;
            cnt += __popc(bal);
        }
    }
    if (lane == 0) s_cnt[w] = cnt < 16 ? cnt : 16;
    __syncthreads();

    if (tid == 0) {
        int tot = 0;
        for (int ww = 0; ww < 8 && tot < 16; ++ww)
            for (int j = 0; j < s_cnt[ww] && tot < 16; ++j)
                s_idx[tot++] = s_cand[ww * 16 + j];
        if (tot == 0) { for (int j = 0; j < 16; ++j) s_idx[j] = 0; }
        else          { for (int j = tot; j < 16; ++j) s_idx[j] = s_idx[0]; }
    }
    __syncthreads();

    if (tid < 16) {
        int p = s_idx[tid];
        float gx = xb[p * 3 + 0], gy = xb[p * 3 + 1], gz = xb[p * 3 + 2];
        float dx = (gx - qx) / 0.05f;
        float dy = (gy - qy) / 0.05f;
        float dz = (gz - qz) / 0.05f;
        s_co[tid * 3 + 0] = dx * R00 + dy * R10 + dz * R20;
        s_co[tid * 3 + 1] = dx * R01 + dy * R11 + dz * R21;
        s_co[tid * 3 + 2] = dx * R02 + dy * R12 + dz * R22;
    }
    __syncthreads();

    __half* H = g_H0 + (size_t)q * 16 * K1P;
    for (int t = tid; t < 16 * 32; t += 256) {
        int n = t >> 5, c = 256 + (t & 31);
        float v = (c < 259) ? s_co[n * 3 + (c - 256)] : 0.f;
        H[n * K1P + c] = __float2half(v);
    }
    const __half* ft = g_featT + (size_t)b * NN * CC;
    for (int t = tid; t < 16 * 64; t += 256) {
        int n = t >> 6, cs = t & 63;
        uint2 v = *(const uint2*)(ft + (size_t)s_idx[n] * CC + cs * 4);
        *(uint2*)(H + n * K1P + cs * 4) = v;
    }
}

// ---------------- tensor-core GEMM:  C = relu(bn(A @ W^T + b)) --------------
__device__ __forceinline__ void ldsm_x4(unsigned& r0, unsigned& r1,
                                        unsigned& r2, unsigned& r3,
                                        const __half* p)
{
    unsigned a = (unsigned)__cvta_generic_to_shared(p);
    asm volatile("ldmatrix.sync.aligned.m8n8.x4.shared.b16 {%0,%1,%2,%3}, [%4];"
                 : "=r"(r0), "=r"(r1), "=r"(r2), "=r"(r3) : "r"(a));
}

__device__ __forceinline__ void mma16816(float* c, const unsigned* a,
                                         unsigned b0, unsigned b1)
{
    asm volatile(
        "mma.sync.aligned.m16n8k16.row.col.f32.f16.f16.f32 "
        "{%0,%1,%2,%3},{%4,%5,%6,%7},{%8,%9},{%0,%1,%2,%3};"
        : "+f"(c[0]), "+f"(c[1]), "+f"(c[2]), "+f"(c[3])
        : "r"(a[0]), "r"(a[1]), "r"(a[2]), "r"(a[3]), "r"(b0), "r"(b1));
}

__device__ __forceinline__ void cp16(void* sdst, const void* gsrc)
{
    unsigned s = (unsigned)__cvta_generic_to_shared(sdst);
    asm volatile("cp.async.cg.shared.global [%0], [%1], 16;" :: "r"(s), "l"(gsrc));
}
__device__ __forceinline__ void cp_commit()
{
    asm volatile("cp.async.commit_group;");
}
template<int N>
__device__ __forceinline__ void cp_wait()
{
    asm volatile("cp.async.wait_group %0;" :: "n"(N));
}

// CTA tile 128(M) x 128(N), 4 warps (2x2), warp tile 64x64, K-step 32,
// cp.async double-buffered.  smem rows padded to 40 halfs (conflict-free LDSM).
template<bool OUT_HALF>
__global__ void __launch_bounds__(128)
gemm_kernel(const __half* __restrict__ A, int lda,
            const __half* __restrict__ W, int ldw, int K,
            const float* __restrict__ bias, const float* __restrict__ gain,
            const float* __restrict__ beta, void* __restrict__ outp, int ldo)
{
    __shared__ __half As[2][128 * 40];
    __shared__ __half Ws[2][128 * 40];

    const int tid = threadIdx.x, lane = tid & 31, warp = tid >> 5;
    const int wm = warp & 1, wn = warp >> 1;
    const size_t m0 = (size_t)blockIdx.x * 128;
    const int n0 = blockIdx.y * 128;

    float acc[4][8][4] = {};

    const int lr = tid >> 2;        // 0..31 base row
    const int lc = (tid & 3) * 8;   // chunk offset in halfs (16B)

    const __half* Ag = A + (m0 + lr) * lda + lc;
    const __half* Wg = W + (size_t)(n0 + lr) * ldw + lc;

    const int KT = K >> 5;

    // preload tile 0
#pragma unroll
    for (int ps = 0; ps < 4; ++ps) {
        cp16(&As[0][(lr + ps * 32) * 40 + lc], Ag + (size_t)(ps * 32) * lda);
        cp16(&Ws[0][(lr + ps * 32) * 40 + lc], Wg + (size_t)(ps * 32) * ldw);
    }
    cp_commit();

    for (int kt = 0; kt < KT; ++kt) {
        int buf = kt & 1;
        if (kt + 1 < KT) {
            const __half* Agn = Ag + (kt + 1) * 32;
            const __half* Wgn = Wg + (kt + 1) * 32;
#pragma unroll
            for (int ps = 0; ps < 4; ++ps) {
                cp16(&As[buf ^ 1][(lr + ps * 32) * 40 + lc], Agn + (size_t)(ps * 32) * lda);
                cp16(&Ws[buf ^ 1][(lr + ps * 32) * 40 + lc], Wgn + (size_t)(ps * 32) * ldw);
            }
            cp_commit();
            cp_wait<1>();
        } else {
            cp_wait<0>();
        }
        __syncthreads();

#pragma unroll
        for (int kb = 0; kb < 32; kb += 16) {
            unsigned am[4][4];
#pragma unroll
            for (int mi = 0; mi < 4; ++mi)
                ldsm_x4(am[mi][0], am[mi][1], am[mi][2], am[mi][3],
                        &As[buf][(wm * 64 + mi * 16 + (lane & 15)) * 40 + kb + (lane >> 4) * 8]);
            unsigned b0[8], b1[8];
#pragma unroll
            for (int p = 0; p < 4; ++p) {
                unsigned t0, t1, t2, t3;
                ldsm_x4(t0, t1, t2, t3,
                        &Ws[buf][(wn * 64 + p * 16 + (lane & 15)) * 40 + kb + (lane >> 4) * 8]);
                b0[2 * p] = t0; b0[2 * p + 1] = t1;
                b1[2 * p] = t2; b1[2 * p + 1] = t3;
            }
#pragma unroll
            for (int mi = 0; mi < 4; ++mi)
#pragma unroll
                for (int ni = 0; ni < 8; ++ni)
                    mma16816(acc[mi][ni], am[mi], b0[ni], b1[ni]);
        }
        __syncthreads();
    }

    const float inv = rsqrtf(1.f + 1e-5f);
#pragma unroll
    for (int mi = 0; mi < 4; ++mi) {
        size_t row = m0 + wm * 64 + mi * 16 + (lane >> 2);
#pragma unroll
        for (int ni = 0; ni < 8; ++ni) {
            int col = n0 + wn * 64 + ni * 8 + (lane & 3) * 2;
            float s0 = gain[col] * inv,  s1 = gain[col + 1] * inv;
            float bi0 = bias[col],       bi1 = bias[col + 1];
            float be0 = beta[col],       be1 = beta[col + 1];
            float v00 = fmaxf(fmaf(acc[mi][ni][0] + bi0, s0, be0), 0.f);
            float v01 = fmaxf(fmaf(acc[mi][ni][1] + bi1, s1, be1), 0.f);
            float v10 = fmaxf(fmaf(acc[mi][ni][2] + bi0, s0, be0), 0.f);
            float v11 = fmaxf(fmaf(acc[mi][ni][3] + bi1, s1, be1), 0.f);
            if (OUT_HALF) {
                __half* o = (__half*)outp;
                *(__half2*)(o + row * ldo + col)       = __floats2half2_rn(v00, v01);
                *(__half2*)(o + (row + 8) * ldo + col) = __floats2half2_rn(v10, v11);
            } else {
                float* o = (float*)outp;
                *(float2*)(o + row * ldo + col)        = make_float2(v00, v01);
                *(float2*)(o + (row + 8) * ldo + col)  = make_float2(v10, v11);
            }
        }
    }
}

// ---------------- head: maxpool + c1/c2/c3 via warp-shuffle dot products ---
__device__ __forceinline__ float warp_dot8(const float* v, const float* Wrow, int lane)
{
    const float4* Wp = (const float4*)(Wrow + lane * 8);
    float4 w0 = Wp[0], w1 = Wp[1];
    float a = v[0] * w0.x + v[1] * w0.y + v[2] * w0.z + v[3] * w0.w
            + v[4] * w1.x + v[5] * w1.y + v[6] * w1.z + v[7] * w1.w;
    a += __shfl_xor_sync(0xffffffffu, a, 16);
    a += __shfl_xor_sync(0xffffffffu, a, 8);
    a += __shfl_xor_sync(0xffffffffu, a, 4);
    a += __shfl_xor_sync(0xffffffffu, a, 2);
    a += __shfl_xor_sync(0xffffffffu, a, 1);
    return a;
}

__device__ __forceinline__ void head_layer(
    const float* __restrict__ src, const float* __restrict__ W,
    const float* __restrict__ bias, const float* __restrict__ gain,
    const float* __restrict__ beta, float* __restrict__ dst,
    int lane, int warp)
{
    float v[8];
    *(float4*)(v)     = *(const float4*)(src + lane * 8);
    *(float4*)(v + 4) = *(const float4*)(src + lane * 8 + 4);
    const float inv = rsqrtf(1.f + 1e-5f);
#pragma unroll 4
    for (int oo = 0; oo < 32; ++oo) {
        int o = warp * 32 + oo;
        float a = warp_dot8(v, W + o * 256, lane);
        if (lane == oo) {
            float val = (a + bias[o]) * (gain[o] * inv) + beta[o];
            dst[o] = fmaxf(val, 0.f);
        }
    }
}

__global__ void __launch_bounds__(256)
head_kernel(const float* __restrict__ cw1, const float* __restrict__ cb1,
            const float* __restrict__ cg1, const float* __restrict__ cbe1,
            const float* __restrict__ cw2, const float* __restrict__ cb2,
            const float* __restrict__ cg2, const float* __restrict__ cbe2,
            const float* __restrict__ cw3, const float* __restrict__ cb3,
            float* __restrict__ out)
{
    __shared__ float va[256], vb[256];
    const int q = blockIdx.x, tid = threadIdx.x;
    const int lane = tid & 31, warp = tid >> 5;

    const float* a3 = g_act3 + (size_t)q * 16 * 256;
    float mx = a3[tid];
#pragma unroll
    for (int n = 1; n < NSS; ++n) mx = fmaxf(mx, a3[n * 256 + tid]);
    va[tid] = mx;
    __syncthreads();

    head_layer(va, cw1, cb1, cg1, cbe1, vb, lane, warp);
    __syncthreads();
    head_layer(vb, cw2, cb2, cg2, cbe2, va, lane, warp);
    __syncthreads();

    // c3: 96 outputs, 12 per warp
    {
        float v[8];
        *(float4*)(v)     = *(const float4*)(va + lane * 8);
        *(float4*)(v + 4) = *(const float4*)(va + lane * 8 + 4);
#pragma unroll
        for (int oo = 0; oo < 12; ++oo) {
            int o = warp * 12 + oo;
            float a = warp_dot8(v, cw3 + o * 256, lane);
            if (lane == oo) out[(size_t)q * OUTC + o] = a + cb3[o];
        }
    }
}

// ---------------- launch ----------------------------------------------------
extern "C" void kernel_launch(void* const* d_in, const int* in_sizes, int n_in,
                              void* d_out, int out_size)
{
    const float* xyz      = (const float*)d_in[0];
    const float* new_xyz  = (const float*)d_in[1];
    const float* view_rot = (const float*)d_in[2];
    const float* features = (const float*)d_in[3];
    const float* w1  = (const float*)d_in[4];
    const float* b1  = (const float*)d_in[5];
    const float* g1  = (const float*)d_in[6];
    const float* be1 = (const float*)d_in[7];
    const float* w2  = (const float*)d_in[8];
    const float* b2  = (const float*)d_in[9];
    const float* g2  = (const float*)d_in[10];
    const float* be2 = (const float*)d_in[11];
    const float* w3  = (const float*)d_in[12];
    const float* b3  = (const float*)d_in[13];
    const float* g3  = (const float*)d_in[14];
    const float* be3 = (const float*)d_in[15];
    const float* cw1 = (const float*)d_in[16];
    const float* cb1 = (const float*)d_in[17];
    const float* cg1 = (const float*)d_in[18];
    const float* cbe1= (const float*)d_in[19];
    const float* cw2 = (const float*)d_in[20];
    const float* cb2 = (const float*)d_in[21];
    const float* cg2 = (const float*)d_in[22];
    const float* cbe2= (const float*)d_in[23];
    const float* cw3 = (const float*)d_in[24];
    const float* cb3 = (const float*)d_in[25];
    float* out = (float*)d_out;

    __half *fT, *h0, *a1, *a2, *w1h, *w2h, *w3h;
    float* a3;
    cudaGetSymbolAddress((void**)&fT,  g_featT);
    cudaGetSymbolAddress((void**)&h0,  g_H0);
    cudaGetSymbolAddress((void**)&a1,  g_act1);
    cudaGetSymbolAddress((void**)&a2,  g_act2);
    cudaGetSymbolAddress((void**)&a3,  g_act3);
    cudaGetSymbolAddress((void**)&w1h, g_w1h);
    cudaGetSymbolAddress((void**)&w2h, g_w2h);
    cudaGetSymbolAddress((void**)&w3h, g_w3h);

    prep_weights<<<1344, 256>>>(w1, w2, w3);
    transpose_feat<<<dim3(NN / 32, CC / 32, BB), dim3(32, 8)>>>(features);
    gather_kernel<<<BB * SS, 256>>>(xyz, new_xyz, view_rot);

    gemm_kernel<true ><<<dim3(MROWS / 128, 4), 128>>>(h0, K1P, w1h, K1P, K1P, b1, g1, be1, a1, 512);
    gemm_kernel<true ><<<dim3(MROWS / 128, 2), 128>>>(a1, 512, w2h, 512, 512, b2, g2, be2, a2, 256);
    gemm_kernel<false><<<dim3(MROWS / 128, 2), 128>>>(a2, 256, w3h, 256, 256, b3, g3, be3, a3, 256);

    head_kernel<<<BB * SS, 256>>>(cw1, cb1, cg1, cbe1, cw2, cb2, cg2, cbe2, cw3, cb3, out);
}

// round 5
// speedup vs baseline: 6.2822x; 1.3228x over previous
#include <cuda_runtime.h>
#include <cuda_fp16.h>
#include <cstdint>

#define BB 2
#define NN 20000
#define SS 1024
#define CC 256
#define NSS 16
#define OUTC 96
#define MROWS (BB*SS*NSS)   /* 32768 */
#define K1P 288             /* 259 padded to multiple of 32 */
#define NQ  (BB*SS)         /* 2048 */

// ---------------- scratch (static device globals; no runtime alloc) --------
__device__ __half g_featT[(size_t)BB*NN*CC];
__device__ __half g_H0[(size_t)MROWS*K1P];
__device__ __half g_act1[(size_t)MROWS*512];
__device__ __half g_act2[(size_t)MROWS*256];
__device__ __half g_act3[(size_t)MROWS*256];
__device__ __half g_pooled[(size_t)NQ*256];
__device__ __half g_h1[(size_t)NQ*256];
__device__ __half g_h2[(size_t)NQ*256];
__device__ float  g_hout[(size_t)NQ*128];
__device__ __half g_w1h[512*K1P];
__device__ __half g_w2h[256*512];
__device__ __half g_w3h[256*256];
__device__ __half g_cw1h[256*256];
__device__ __half g_cw2h[256*256];
__device__ __half g_cw3h[128*256];
__device__ float  g_cb3p[128];

// ---------------- weight prep ------------------------------------------------
__global__ void prep_weights(const float* __restrict__ w1,
                             const float* __restrict__ w2,
                             const float* __restrict__ w3,
                             const float* __restrict__ cw1,
                             const float* __restrict__ cw2,
                             const float* __restrict__ cw3,
                             const float* __restrict__ cb3)
{
    int i = blockIdx.x * 256 + threadIdx.x;
    if (i < 512 * K1P) {
        int o = i / K1P, k = i % K1P;
        float v = 0.f;
        if (k < 256)      v = w1[o * 259 + 3 + k];
        else if (k < 259) v = w1[o * 259 + (k - 256)];
        g_w1h[i] = __float2half(v);
    }
    if (i < 256 * 512) g_w2h[i] = __float2half(w2[i]);
    if (i < 256 * 256) {
        g_w3h[i]  = __float2half(w3[i]);
        g_cw1h[i] = __float2half(cw1[i]);
        g_cw2h[i] = __float2half(cw2[i]);
    }
    if (i < 128 * 256) {
        int o = i >> 8, k = i & 255;
        g_cw3h[i] = __float2half(o < OUTC ? cw3[o * 256 + k] : 0.f);
    }
    if (i < 128) g_cb3p[i] = (i < OUTC) ? cb3[i] : 0.f;
}

// ---------------- transpose features [b][c][n] -> [b][n][c] fp16 ------------
__global__ void transpose_feat(const float* __restrict__ feat)
{
    __shared__ float tile[32][33];
    int b = blockIdx.z, n0 = blockIdx.x * 32, c0 = blockIdx.y * 32;
    int tx = threadIdx.x, ty = threadIdx.y;
    const float* fb = feat + (size_t)b * CC * NN;
#pragma unroll
    for (int i = 0; i < 4; ++i) {
        int c = c0 + ty + i * 8;
        tile[ty + i * 8][tx] = fb[(size_t)c * NN + n0 + tx];
    }
    __syncthreads();
    __half* ft = g_featT + (size_t)b * NN * CC;
#pragma unroll
    for (int i = 0; i < 4; ++i) {
        int n = n0 + ty + i * 8;
        ft[(size_t)n * CC + c0 + tx] = __float2half(tile[tx][ty + i * 8]);
    }
}

// ---------------- ball query + gather into H0 (proven full-scan path) -------
__global__ void __launch_bounds__(256)
gather_kernel(const float* __restrict__ xyz, const float* __restrict__ new_xyz,
              const float* __restrict__ view_rot)
{
    __shared__ int   s_cand[8 * 16];
    __shared__ int   s_cnt[8];
    __shared__ int   s_idx[16];
    __shared__ float s_co[16 * 3];

    const int q = blockIdx.x;
    const int b = q >> 10;
    const int tid = threadIdx.x, lane = tid & 31, w = tid >> 5;

    const float* vr = view_rot + (size_t)q * 9;
    float R00 = vr[0], R01 = vr[1], R02 = vr[2];
    float R10 = vr[3], R11 = vr[4], R12 = vr[5];
    float R20 = vr[6], R21 = vr[7], R22 = vr[8];
    float qx = new_xyz[q * 3 + 0], qy = new_xyz[q * 3 + 1], qz = new_xyz[q * 3 + 2];
    float d0 = R00 * qx + R01 * qy + R02 * qz;
    float d1 = R10 * qx + R11 * qy + R12 * qz;
    float d2 = R20 * qx + R21 * qy + R22 * qz;

    const float* xb = xyz + (size_t)b * NN * 3;

    // warp-parallel ordered compaction: warp w scans [w*2500, (w+1)*2500)
    const int start = w * 2500;
    int cnt = 0;
    for (int i = 0; i < 79 && cnt < 16; ++i) {
        int p = start + i * 32 + lane;
        bool mk = false;
        if (p < start + 2500) {
            float x = xb[p * 3 + 0], y = xb[p * 3 + 1], z = xb[p * 3 + 2];
            float xr = fmaf(R00, x, fmaf(R01, y, R02 * z)) - d0;
            float yr = fmaf(R10, x, fmaf(R11, y, R12 * z)) - d1;
            float zr = fmaf(R20, x, fmaf(R21, y, R22 * z)) - d2;
            mk = (yr * yr + zr * zr < 0.05f * 0.05f) && (xr > -0.02f) && (xr < 0.04f);
        }
        unsigned bal = __ballot_sync(0xffffffffu, mk);
        if (bal) {
            int pos = cnt + __popc(bal & ((1u << lane) - 1u));
            if (mk && pos < 16) s_cand[w * 16 + pos] = p;
            cnt += __popc(bal);
        }
    }
    if (lane == 0) s_cnt[w] = cnt < 16 ? cnt : 16;
    __syncthreads();

    if (tid == 0) {
        int tot = 0;
        for (int ww = 0; ww < 8 && tot < 16; ++ww)
            for (int j = 0; j < s_cnt[ww] && tot < 16; ++j)
                s_idx[tot++] = s_cand[ww * 16 + j];
        if (tot == 0) { for (int j = 0; j < 16; ++j) s_idx[j] = 0; }
        else          { for (int j = tot; j < 16; ++j) s_idx[j] = s_idx[0]; }
    }
    __syncthreads();

    if (tid < 16) {
        int p = s_idx[tid];
        float gx = xb[p * 3 + 0], gy = xb[p * 3 + 1], gz = xb[p * 3 + 2];
        float dx = (gx - qx) / 0.05f;
        float dy = (gy - qy) / 0.05f;
        float dz = (gz - qz) / 0.05f;
        s_co[tid * 3 + 0] = dx * R00 + dy * R10 + dz * R20;
        s_co[tid * 3 + 1] = dx * R01 + dy * R11 + dz * R21;
        s_co[tid * 3 + 2] = dx * R02 + dy * R12 + dz * R22;
    }
    __syncthreads();

    __half* H = g_H0 + (size_t)q * 16 * K1P;
    for (int t = tid; t < 16 * 32; t += 256) {
        int n = t >> 5, c = 256 + (t & 31);
        float v = (c < 259) ? s_co[n * 3 + (c - 256)] : 0.f;
        H[n * K1P + c] = __float2half(v);
    }
    const __half* ft = g_featT + (size_t)b * NN * CC;
    for (int t = tid; t < 16 * 64; t += 256) {
        int n = t >> 6, cs = t & 63;
        uint2 v = *(const uint2*)(ft + (size_t)s_idx[n] * CC + cs * 4);
        *(uint2*)(H + n * K1P + cs * 4) = v;
    }
}

// ---------------- tensor-core GEMM -------------------------------------------
__device__ __forceinline__ void ldsm_x4(unsigned& r0, unsigned& r1,
                                        unsigned& r2, unsigned& r3,
                                        const __half* p)
{
    unsigned a = (unsigned)__cvta_generic_to_shared(p);
    asm volatile("ldmatrix.sync.aligned.m8n8.x4.shared.b16 {%0,%1,%2,%3}, [%4];"
                 : "=r"(r0), "=r"(r1), "=r"(r2), "=r"(r3) : "r"(a));
}
__device__ __forceinline__ void mma16816(float* c, const unsigned* a,
                                         unsigned b0, unsigned b1)
{
    asm volatile(
        "mma.sync.aligned.m16n8k16.row.col.f32.f16.f16.f32 "
        "{%0,%1,%2,%3},{%4,%5,%6,%7},{%8,%9},{%0,%1,%2,%3};"
        : "+f"(c[0]), "+f"(c[1]), "+f"(c[2]), "+f"(c[3])
        : "r"(a[0]), "r"(a[1]), "r"(a[2]), "r"(a[3]), "r"(b0), "r"(b1));
}
__device__ __forceinline__ void cp16(void* sdst, const void* gsrc)
{
    unsigned s = (unsigned)__cvta_generic_to_shared(sdst);
    asm volatile("cp.async.cg.shared.global [%0], [%1], 16;" :: "r"(s), "l"(gsrc));
}
__device__ __forceinline__ void cp_commit() { asm volatile("cp.async.commit_group;"); }
template<int N>
__device__ __forceinline__ void cp_wait() { asm volatile("cp.async.wait_group %0;" :: "n"(N)); }

#define STG_F (128*40)   /* halfs per stage per operand */

// CTA 128x128, 4 warps (2x2), warp tile 64x64, 3-stage cp.async pipeline.
template<bool OUT_HALF, bool DO_BN>
__global__ void __launch_bounds__(128, 3)
gemm_kernel(const __half* __restrict__ A, int lda,
            const __half* __restrict__ W, int ldw, int K,
            const float* __restrict__ bias, const float* __restrict__ gain,
            const float* __restrict__ beta, void* __restrict__ outp, int ldo)
{
    extern __shared__ __half dsm[];
    __half* Asb = dsm;              // 3 stages
    __half* Wsb = dsm + 3 * STG_F;

    const int tid = threadIdx.x, lane = tid & 31, warp = tid >> 5;
    const int wm = warp & 1, wn = warp >> 1;
    const size_t m0 = (size_t)blockIdx.x * 128;
    const int n0 = blockIdx.y * 128;

    float acc[4][8][4] = {};

    const int lr = tid >> 2;
    const int lc = (tid & 3) * 8;
    const __half* Ag = A + (m0 + lr) * lda + lc;
    const __half* Wg = W + (size_t)(n0 + lr) * ldw + lc;
    const int KT = K >> 5;

#define STAGE_LOAD(st, kt)                                                    \
    {                                                                         \
        const __half* ap = Ag + (kt) * 32;                                    \
        const __half* wp = Wg + (kt) * 32;                                    \
        __half* as = Asb + (st) * STG_F;                                      \
        __half* ws = Wsb + (st) * STG_F;                                      \
        _Pragma("unroll")                                                     \
        for (int ps = 0; ps < 4; ++ps) {                                      \
            cp16(as + (lr + ps * 32) * 40 + lc, ap + (size_t)(ps * 32) * lda);\
            cp16(ws + (lr + ps * 32) * 40 + lc, wp + (size_t)(ps * 32) * ldw);\
        }                                                                     \
        cp_commit();                                                          \
    }

    STAGE_LOAD(0, 0)
    STAGE_LOAD(1, 1)

    int st = 0;
    for (int kt = 0; kt < KT; ++kt) {
        if (kt + 1 < KT) cp_wait<1>(); else cp_wait<0>();
        __syncthreads();
        if (kt + 2 < KT) {
            int st2 = st + 2; if (st2 >= 3) st2 -= 3;
            STAGE_LOAD(st2, kt + 2)
        }
        const __half* as = Asb + st * STG_F;
        const __half* ws = Wsb + st * STG_F;
#pragma unroll
        for (int kb = 0; kb < 32; kb += 16) {
            unsigned am[4][4];
#pragma unroll
            for (int mi = 0; mi < 4; ++mi)
                ldsm_x4(am[mi][0], am[mi][1], am[mi][2], am[mi][3],
                        as + (wm * 64 + mi * 16 + (lane & 15)) * 40 + kb + (lane >> 4) * 8);
            unsigned b0[8], b1[8];
#pragma unroll
            for (int p = 0; p < 4; ++p) {
                unsigned t0, t1, t2, t3;
                ldsm_x4(t0, t1, t2, t3,
                        ws + (wn * 64 + p * 16 + (lane & 15)) * 40 + kb + (lane >> 4) * 8);
                b0[2 * p] = t0; b0[2 * p + 1] = t1;
                b1[2 * p] = t2; b1[2 * p + 1] = t3;
            }
#pragma unroll
            for (int mi = 0; mi < 4; ++mi)
#pragma unroll
                for (int ni = 0; ni < 8; ++ni)
                    mma16816(acc[mi][ni], am[mi], b0[ni], b1[ni]);
        }
        ++st; if (st == 3) st = 0;
    }

    const float inv = rsqrtf(1.f + 1e-5f);
#pragma unroll
    for (int mi = 0; mi < 4; ++mi) {
        size_t row = m0 + wm * 64 + mi * 16 + (lane >> 2);
#pragma unroll
        for (int ni = 0; ni < 8; ++ni) {
            int col = n0 + wn * 64 + ni * 8 + (lane & 3) * 2;
            float v00, v01, v10, v11;
            if (DO_BN) {
                float s0 = gain[col] * inv,  s1 = gain[col + 1] * inv;
                float bi0 = bias[col],       bi1 = bias[col + 1];
                float be0 = beta[col],       be1 = beta[col + 1];
                v00 = fmaxf(fmaf(acc[mi][ni][0] + bi0, s0, be0), 0.f);
                v01 = fmaxf(fmaf(acc[mi][ni][1] + bi1, s1, be1), 0.f);
                v10 = fmaxf(fmaf(acc[mi][ni][2] + bi0, s0, be0), 0.f);
                v11 = fmaxf(fmaf(acc[mi][ni][3] + bi1, s1, be1), 0.f);
            } else {
                float bi0 = bias[col], bi1 = bias[col + 1];
                v00 = acc[mi][ni][0] + bi0;  v01 = acc[mi][ni][1] + bi1;
                v10 = acc[mi][ni][2] + bi0;  v11 = acc[mi][ni][3] + bi1;
            }
            if (OUT_HALF) {
                __half* o = (__half*)outp;
                *(__half2*)(o + row * ldo + col)       = __floats2half2_rn(v00, v01);
                *(__half2*)(o + (row + 8) * ldo + col) = __floats2half2_rn(v10, v11);
            } else {
                float* o = (float*)outp;
                *(float2*)(o + row * ldo + col)        = make_float2(v00, v01);
                *(float2*)(o + (row + 8) * ldo + col)  = make_float2(v10, v11);
            }
        }
    }
}

// ---------------- maxpool over the 16 neighbors ------------------------------
__global__ void maxpool_kernel()
{
    int q = blockIdx.x, c = threadIdx.x;
    const __half* a = g_act3 + (size_t)q * 16 * 256 + c;
    float mx = __half2float(a[0]);
#pragma unroll
    for (int n = 1; n < NSS; ++n) mx = fmaxf(mx, __half2float(a[n * 256]));
    g_pooled[(size_t)q * 256 + c] = __float2half(mx);
}

// ---------------- copy padded head output -> out ------------------------------
__global__ void copyout_kernel(float* __restrict__ out)
{
    int i = blockIdx.x * 256 + threadIdx.x;
    if (i >= NQ * OUTC) return;
    int q = i / OUTC, o = i % OUTC;
    out[i] = g_hout[(size_t)q * 128 + o];
}

// ---------------- launch ------------------------------------------------------
extern "C" void kernel_launch(void* const* d_in, const int* in_sizes, int n_in,
                              void* d_out, int out_size)
{
    const float* xyz      = (const float*)d_in[0];
    const float* new_xyz  = (const float*)d_in[1];
    const float* view_rot = (const float*)d_in[2];
    const float* features = (const float*)d_in[3];
    const float* w1  = (const float*)d_in[4];
    const float* b1  = (const float*)d_in[5];
    const float* g1  = (const float*)d_in[6];
    const float* be1 = (const float*)d_in[7];
    const float* w2  = (const float*)d_in[8];
    const float* b2  = (const float*)d_in[9];
    const float* g2  = (const float*)d_in[10];
    const float* be2 = (const float*)d_in[11];
    const float* w3  = (const float*)d_in[12];
    const float* b3  = (const float*)d_in[13];
    const float* g3  = (const float*)d_in[14];
    const float* be3 = (const float*)d_in[15];
    const float* cw1 = (const float*)d_in[16];
    const float* cb1 = (const float*)d_in[17];
    const float* cg1 = (const float*)d_in[18];
    const float* cbe1= (const float*)d_in[19];
    const float* cw2 = (const float*)d_in[20];
    const float* cb2 = (const float*)d_in[21];
    const float* cg2 = (const float*)d_in[22];
    const float* cbe2= (const float*)d_in[23];
    const float* cw3 = (const float*)d_in[24];
    const float* cb3 = (const float*)d_in[25];
    float* out = (float*)d_out;

    __half *h0, *a1, *a2, *a3, *pooled, *h1, *h2;
    __half *w1h, *w2h, *w3h, *cw1h, *cw2h, *cw3h;
    float *hout, *cb3p;
    cudaGetSymbolAddress((void**)&h0,   g_H0);
    cudaGetSymbolAddress((void**)&a1,   g_act1);
    cudaGetSymbolAddress((void**)&a2,   g_act2);
    cudaGetSymbolAddress((void**)&a3,   g_act3);
    cudaGetSymbolAddress((void**)&pooled, g_pooled);
    cudaGetSymbolAddress((void**)&h1,   g_h1);
    cudaGetSymbolAddress((void**)&h2,   g_h2);
    cudaGetSymbolAddress((void**)&hout, g_hout);
    cudaGetSymbolAddress((void**)&w1h,  g_w1h);
    cudaGetSymbolAddress((void**)&w2h,  g_w2h);
    cudaGetSymbolAddress((void**)&w3h,  g_w3h);
    cudaGetSymbolAddress((void**)&cw1h, g_cw1h);
    cudaGetSymbolAddress((void**)&cw2h, g_cw2h);
    cudaGetSymbolAddress((void**)&cw3h, g_cw3h);
    cudaGetSymbolAddress((void**)&cb3p, g_cb3p);

    const int SMEM = 6 * STG_F * 2;   // 61440 bytes
    cudaFuncSetAttribute(gemm_kernel<true , true >, cudaFuncAttributeMaxDynamicSharedMemorySize, SMEM);
    cudaFuncSetAttribute(gemm_kernel<false, false>, cudaFuncAttributeMaxDynamicSharedMemorySize, SMEM);

    prep_weights<<<(512 * K1P + 255) / 256, 256>>>(w1, w2, w3, cw1, cw2, cw3, cb3);
    transpose_feat<<<dim3(NN / 32, CC / 32, BB), dim3(32, 8)>>>(features);
    gather_kernel<<<NQ, 256>>>(xyz, new_xyz, view_rot);

    gemm_kernel<true , true ><<<dim3(MROWS / 128, 4), 128, SMEM>>>(h0, K1P, w1h, K1P, K1P, b1, g1, be1, a1, 512);
    gemm_kernel<true , true ><<<dim3(MROWS / 128, 2), 128, SMEM>>>(a1, 512, w2h, 512, 512, b2, g2, be2, a2, 256);
    gemm_kernel<true , true ><<<dim3(MROWS / 128, 2), 128, SMEM>>>(a2, 256, w3h, 256, 256, b3, g3, be3, a3, 256);

    maxpool_kernel<<<NQ, 256>>>();

    gemm_kernel<true , true ><<<dim3(NQ / 128, 2), 128, SMEM>>>(pooled, 256, cw1h, 256, 256, cb1, cg1, cbe1, h1, 256);
    gemm_kernel<true , true ><<<dim3(NQ / 128, 2), 128, SMEM>>>(h1,     256, cw2h, 256, 256, cb2, cg2, cbe2, h2, 256);
    gemm_kernel<false, false><<<dim3(NQ / 128, 1), 128, SMEM>>>(h2,     256, cw3h, 256, 256, cb3p, nullptr, nullptr, hout, 128);

    copyout_kernel<<<(NQ * OUTC + 255) / 256, 256>>>(out);
}